// round 15
// baseline (speedup 1.0000x reference)
#include <cuda_runtime.h>
#include <cuda_bf16.h>
#include <cstdint>
#include <math.h>

#define BATCH 2
#define TLEN 2048
#define DIM 1024
#define HEADS 16
#define DH 64
#define WINDOW 32
#define NTOK (BATCH * TLEN)
#define LN_EPS 1e-5f

// ---------------- scratch (device globals; 96 MB fp32 set) ----------------
__device__ float g_h[(size_t)NTOK * DIM];          // LN output, [tok, DIM]
__device__ float g_qkv[(size_t)NTOK * 3 * DIM];    // [tok, 3*DIM]
__device__ float g_att[(size_t)NTOK * DIM];        // attention output
__device__ float g_proj[(size_t)NTOK * DIM];       // out-proj result

// ---------------- 1) LayerNorm + transpose [B,C,T] -> [tok,C] -------------
__global__ void ln_transpose_kernel(const float* __restrict__ x,
                                    const float* __restrict__ w,
                                    const float* __restrict__ bias) {
    const int b  = blockIdx.y;
    const int t0 = blockIdx.x * 32;
    const int tx = threadIdx.x, ty = threadIdx.y;
    const float* xb = x + (size_t)b * DIM * TLEN;

    float s = 0.f, ss = 0.f;
    for (int c = ty; c < DIM; c += 8) {
        float v = xb[(size_t)c * TLEN + t0 + tx];
        s += v; ss += v * v;
    }
    __shared__ float rs[8][32], rq[8][32];
    rs[ty][tx] = s; rq[ty][tx] = ss;
    __syncthreads();
    __shared__ float mu[32], rstd[32];
    if (ty == 0) {
        float a = 0.f, q = 0.f;
        #pragma unroll
        for (int i = 0; i < 8; i++) { a += rs[i][tx]; q += rq[i][tx]; }
        float m   = a / (float)DIM;
        float var = q / (float)DIM - m * m;
        mu[tx]   = m;
        rstd[tx] = rsqrtf(var + LN_EPS);
    }
    __syncthreads();

    __shared__ float tile[32][33];
    for (int c0 = 0; c0 < DIM; c0 += 32) {
        #pragma unroll
        for (int k = 0; k < 4; k++) {
            int cl = ty + 8 * k;
            tile[cl][tx] = xb[(size_t)(c0 + cl) * TLEN + t0 + tx];
        }
        __syncthreads();
        #pragma unroll
        for (int k = 0; k < 4; k++) {
            int tl = ty + 8 * k;
            int c  = c0 + tx;
            float v = (tile[tx][tl] - mu[tl]) * rstd[tl] * w[c] + bias[c];
            g_h[((size_t)b * TLEN + t0 + tl) * DIM + c] = v;
        }
        __syncthreads();
    }
}

// ---------------- 2/5) bf16x3 GEMM: ldmatrix + double-buffered smem -------
// C[M,N] = A[M,K] * B[K,N]; A [tok,K], B native [K,N].
// CTA tile 128x64xk32, 8 warps (4m x 2n), warp tile 32x32, 2-stage smem.
#define SRA 40   // bf16 k-stride of A smem rows (80B)
#define SRB 72   // bf16 n-stride of B smem rows (144B)
#define OA_HI 0
#define OA_LO 10240
#define OB_HI 20480
#define OB_LO 25088
#define STG_B 29696                 // bytes per stage
#define GEMM_SMEM (2 * STG_B)       // 59392 bytes

#define MMA16816(d, a0, a1, a2, a3, b0, b1)                                   \
    asm volatile("mma.sync.aligned.m16n8k16.row.col.f32.bf16.bf16.f32 "      \
                 "{%0,%1,%2,%3}, {%4,%5,%6,%7}, {%8,%9}, {%0,%1,%2,%3};"     \
                 : "+f"(d[0]), "+f"(d[1]), "+f"(d[2]), "+f"(d[3])             \
                 : "r"(a0), "r"(a1), "r"(a2), "r"(a3), "r"(b0), "r"(b1))

#define LDSM4(r0, r1, r2, r3, addr)                                           \
    asm volatile("ldmatrix.sync.aligned.m8n8.x4.shared.b16 {%0,%1,%2,%3}, [%4];" \
                 : "=r"(r0), "=r"(r1), "=r"(r2), "=r"(r3) : "r"(addr))

#define LDSM4T(r0, r1, r2, r3, addr)                                          \
    asm volatile("ldmatrix.sync.aligned.m8n8.x4.trans.shared.b16 {%0,%1,%2,%3}, [%4];" \
                 : "=r"(r0), "=r"(r1), "=r"(r2), "=r"(r3) : "r"(addr))

__device__ __forceinline__ void split2(float fx, float fy,
                                       uint32_t& hi, uint32_t& lo) {
    __nv_bfloat162 h = __floats2bfloat162_rn(fx, fy);
    float2 hf = __bfloat1622float2(h);
    __nv_bfloat162 l = __floats2bfloat162_rn(fx - hf.x, fy - hf.y);
    hi = *(uint32_t*)&h;
    lo = *(uint32_t*)&l;
}

__global__ __launch_bounds__(256)
void sgemm_tc_kernel(int which, const float* __restrict__ Bm, int N) {
    const float* __restrict__ A = (which == 0) ? g_h : g_att;
    float* __restrict__ C = (which == 0) ? g_qkv : g_proj;
    const int K = DIM;

    extern __shared__ __align__(16) char smx[];
    const uint32_t uS = (uint32_t)__cvta_generic_to_shared(smx);

    const int tid  = threadIdx.x;
    const int warp = tid >> 5, lane = tid & 31;
    const int wm0 = (warp & 3) * 32;
    const int wn0 = (warp >> 2) * 32;
    const int m0 = blockIdx.y * 128;
    const int n0 = blockIdx.x * 64;

    float acc[2][4][4];
    #pragma unroll
    for (int i = 0; i < 2; i++)
        #pragma unroll
        for (int j = 0; j < 4; j++)
            #pragma unroll
            for (int k = 0; k < 4; k++) acc[i][j][k] = 0.f;

    // ldmatrix lane addressing (XOR-8 swizzle matching the stores)
    const int g8 = lane >> 3;
    const int lr = lane & 7;
    const int xo = (g8 & 1) * 8;
    const int aRow = wm0 + (g8 & 1) * 8 + lr;
    const int aCol0 = (g8 >> 1) * 8;
    const int bRow = (g8 & 1) * 8 + lr;
    const int bCol = (wn0 + (g8 >> 1) * 8) ^ xo;

    // loader mapping: A 4 float4/thread, B 2 float4/thread
    const int ar = tid >> 3;
    const int ac = (tid & 7) * 4;
    const int br = tid >> 4;
    const int bc = (tid & 15) * 4;

    float4 pa[4], pb[2];

    #define FETCH(kt)                                                          \
    do {                                                                       \
        int kb = (kt) * 32;                                                    \
        _Pragma("unroll")                                                      \
        for (int i = 0; i < 4; i++)                                            \
            pa[i] = *(const float4*)&A[(size_t)(m0 + ar + 32 * i) * K + kb + ac]; \
        _Pragma("unroll")                                                      \
        for (int i = 0; i < 2; i++)                                            \
            pb[i] = *(const float4*)&Bm[(size_t)(kb + br + 16 * i) * N + n0 + bc]; \
    } while (0)

    #define STORE(st)                                                          \
    do {                                                                       \
        char* sp = smx + (st) * STG_B;                                         \
        _Pragma("unroll")                                                      \
        for (int i = 0; i < 4; i++) {                                          \
            int row = ar + 32 * i;                                             \
            int col = ac ^ (((row >> 3) & 1) * 8);                             \
            uint32_t h0, l0, h1, l1;                                           \
            split2(pa[i].x, pa[i].y, h0, l0);                                  \
            split2(pa[i].z, pa[i].w, h1, l1);                                  \
            *(uint2*)(sp + OA_HI + (row * SRA + col) * 2) = make_uint2(h0, h1);\
            *(uint2*)(sp + OA_LO + (row * SRA + col) * 2) = make_uint2(l0, l1);\
        }                                                                      \
        _Pragma("unroll")                                                      \
        for (int i = 0; i < 2; i++) {                                          \
            int krow = br + 16 * i;                                            \
            int col = bc ^ (((krow >> 3) & 1) * 8);                            \
            uint32_t h0, l0, h1, l1;                                           \
            split2(pb[i].x, pb[i].y, h0, l0);                                  \
            split2(pb[i].z, pb[i].w, h1, l1);                                  \
            *(uint2*)(sp + OB_HI + (krow * SRB + col) * 2) = make_uint2(h0, h1);\
            *(uint2*)(sp + OB_LO + (krow * SRB + col) * 2) = make_uint2(l0, l1);\
        }                                                                      \
    } while (0)

    const int ntiles = K / 32;
    FETCH(0);
    STORE(0);
    __syncthreads();
    FETCH(1);

    for (int kt = 0; kt < ntiles; kt++) {
        const int cur = kt & 1;
        const uint32_t uStage = uS + cur * STG_B;

        #pragma unroll
        for (int ks = 0; ks < 2; ks++) {
            uint32_t bh[4][2], bl[4][2];
            #pragma unroll
            for (int p = 0; p < 2; p++) {
                uint32_t ba = (uint32_t)(((bRow + ks * 16) * SRB + bCol + p * 16) * 2);
                LDSM4T(bh[2 * p][0], bh[2 * p][1], bh[2 * p + 1][0], bh[2 * p + 1][1],
                       uStage + OB_HI + ba);
                LDSM4T(bl[2 * p][0], bl[2 * p][1], bl[2 * p + 1][0], bl[2 * p + 1][1],
                       uStage + OB_LO + ba);
            }
            #pragma unroll
            for (int mt = 0; mt < 2; mt++) {
                uint32_t aa = (uint32_t)(((aRow + mt * 16) * SRA + ((aCol0 + ks * 16) ^ xo)) * 2);
                uint32_t a0, a1, a2, a3, l0, l1, l2, l3;
                LDSM4(a0, a1, a2, a3, uStage + OA_HI + aa);
                LDSM4(l0, l1, l2, l3, uStage + OA_LO + aa);
                #pragma unroll
                for (int nt = 0; nt < 4; nt++) {
                    MMA16816(acc[mt][nt], a0, a1, a2, a3, bh[nt][0], bh[nt][1]);
                    MMA16816(acc[mt][nt], a0, a1, a2, a3, bl[nt][0], bl[nt][1]);
                    MMA16816(acc[mt][nt], l0, l1, l2, l3, bh[nt][0], bh[nt][1]);
                }
            }
        }
        if (kt + 1 < ntiles) {
            STORE(cur ^ 1);             // interleaves with MMA stream above
            if (kt + 2 < ntiles) FETCH(kt + 2);
        }
        __syncthreads();
    }
    #undef FETCH
    #undef STORE

    const int r  = lane >> 2;
    const int c2 = (lane & 3) * 2;
    #pragma unroll
    for (int mt = 0; mt < 2; mt++)
        #pragma unroll
        for (int nt = 0; nt < 4; nt++) {
            int row = m0 + wm0 + mt * 16 + r;
            int col = n0 + wn0 + nt * 8 + c2;
            float2 v0 = make_float2(acc[mt][nt][0], acc[mt][nt][1]);
            float2 v1 = make_float2(acc[mt][nt][2], acc[mt][nt][3]);
            *(float2*)&C[(size_t)row * N + col]       = v0;
            *(float2*)&C[(size_t)(row + 8) * N + col] = v1;
        }
}

// ---------------- 4) windowed causal attention + fused RoPE ---------------
// Vectorized: float4 QK dot, float2 PV reads. Ks/Vs stride 68 (16B aligned).
__global__ __launch_bounds__(256)
void attn_kernel() {
    const int t0 = blockIdx.x * 32;
    const int bh = blockIdx.y;
    const int b = bh / HEADS, h = bh % HEADS;

    __shared__ __align__(16) float Qs[32][64];
    __shared__ __align__(16) float Ks[64][68];
    __shared__ __align__(16) float Vs[64][68];

    const int tid = threadIdx.x;
    const float FREQ = 9.210340371976184f / 32.0f;   // ln(10000)/32

    for (int i = tid; i < 32 * 32; i += 256) {
        int q = i >> 5, d = i & 31;
        int tpos = t0 + q;
        float inv = expf(-(float)d * FREQ);
        float sn, cs;
        sincosf((float)tpos * inv, &sn, &cs);
        size_t base = ((size_t)(b * TLEN + tpos)) * (3 * DIM) + h * DH + d;
        float v1 = g_qkv[base];
        float v2 = g_qkv[base + 32];
        Qs[q][d]      = v1 * cs - v2 * sn;
        Qs[q][d + 32] = v2 * cs + v1 * sn;
    }
    for (int i = tid; i < 63 * 32; i += 256) {
        int rr = i >> 5, d = i & 31;
        int kpos = t0 - 31 + rr;
        float k1 = 0.f, k2 = 0.f;
        if (kpos >= 0) {
            float inv = expf(-(float)d * FREQ);
            float sn, cs;
            sincosf((float)kpos * inv, &sn, &cs);
            size_t off = ((size_t)(b * TLEN + kpos)) * (3 * DIM) + DIM + h * DH + d;
            float v1 = g_qkv[off];
            float v2 = g_qkv[off + 32];
            k1 = v1 * cs - v2 * sn;
            k2 = v2 * cs + v1 * sn;
        }
        Ks[rr][d]      = k1;
        Ks[rr][d + 32] = k2;
    }
    for (int i = tid; i < 63 * 64; i += 256) {
        int rr = i >> 6, d = i & 63;
        int kpos = t0 - 31 + rr;
        float vv = 0.f;
        if (kpos >= 0)
            vv = g_qkv[((size_t)(b * TLEN + kpos)) * (3 * DIM) + 2 * DIM + h * DH + d];
        Vs[rr][d] = vv;
    }
    __syncthreads();

    const int warp = tid >> 5, lane = tid & 31;
    #pragma unroll
    for (int j = 0; j < 4; j++) {
        const int ql   = warp * 4 + j;
        const int qpos = t0 + ql;
        const int rr   = ql + lane;
        const int kpos = qpos - 31 + lane;
        const bool valid = (kpos >= 0);

        const float4* qp = (const float4*)&Qs[ql][0];
        const float4* kp = (const float4*)&Ks[rr][0];
        float s = 0.f;
        #pragma unroll
        for (int d = 0; d < 16; d++) {
            float4 qa = qp[d], ka = kp[d];
            s = fmaf(qa.x, ka.x, s);
            s = fmaf(qa.y, ka.y, s);
            s = fmaf(qa.z, ka.z, s);
            s = fmaf(qa.w, ka.w, s);
        }
        s *= 0.125f;
        s = valid ? s : -INFINITY;

        float m = s;
        #pragma unroll
        for (int o = 16; o; o >>= 1) m = fmaxf(m, __shfl_xor_sync(0xffffffffu, m, o));
        float p = valid ? expf(s - m) : 0.f;
        float sum = p;
        #pragma unroll
        for (int o = 16; o; o >>= 1) sum += __shfl_xor_sync(0xffffffffu, sum, o);
        p /= sum;

        float o0 = 0.f, o1 = 0.f;
        #pragma unroll
        for (int jj = 0; jj < 32; jj++) {
            float pj = __shfl_sync(0xffffffffu, p, jj);
            float2 vv = *(const float2*)&Vs[ql + jj][2 * lane];
            o0 = fmaf(pj, vv.x, o0);
            o1 = fmaf(pj, vv.y, o1);
        }
        size_t oo = ((size_t)(b * TLEN + qpos)) * DIM + h * DH + 2 * lane;
        g_att[oo]     = o0;
        g_att[oo + 1] = o1;
    }
}

// ---------------- 6) transpose + residual ----------------------------------
__global__ void add_transpose_kernel(const float* __restrict__ x,
                                     float* __restrict__ out) {
    const int b  = blockIdx.z;
    const int t0 = blockIdx.x * 32, c0 = blockIdx.y * 32;
    const int tx = threadIdx.x, ty = threadIdx.y;
    __shared__ float tile[32][33];
    #pragma unroll
    for (int k = 0; k < 4; k++) {
        int tl = ty + 8 * k;
        tile[tl][tx] = g_proj[((size_t)(b * TLEN + t0 + tl)) * DIM + c0 + tx];
    }
    __syncthreads();
    #pragma unroll
    for (int k = 0; k < 4; k++) {
        int cl = ty + 8 * k;
        size_t idx = ((size_t)b * DIM + c0 + cl) * TLEN + t0 + tx;
        out[idx] = tile[tx][cl] + x[idx];
    }
}

// ---------------- launch ---------------------------------------------------
extern "C" void kernel_launch(void* const* d_in, const int* in_sizes, int n_in,
                              void* d_out, int out_size) {
    const float* x     = (const float*)d_in[0];
    const float* ln_w  = (const float*)d_in[1];
    const float* ln_b  = (const float*)d_in[2];
    const float* w_qkv = (const float*)d_in[3];
    const float* w_out = (const float*)d_in[4];
    float* out = (float*)d_out;

    cudaFuncSetAttribute(sgemm_tc_kernel,
                         cudaFuncAttributeMaxDynamicSharedMemorySize, GEMM_SMEM);

    ln_transpose_kernel<<<dim3(TLEN / 32, BATCH), dim3(32, 8)>>>(x, ln_w, ln_b);

    // QKV GEMM: [4096,1024] x [1024,3072] -> g_qkv
    sgemm_tc_kernel<<<dim3((3 * DIM) / 64, NTOK / 128), 256, GEMM_SMEM>>>(0, w_qkv, 3 * DIM);

    // attention with fused RoPE -> g_att
    attn_kernel<<<dim3(TLEN / 32, BATCH * HEADS), 256>>>();

    // out projection: [4096,1024] x [1024,1024] -> g_proj
    sgemm_tc_kernel<<<dim3(DIM / 64, NTOK / 128), 256, GEMM_SMEM>>>(1, w_out, DIM);

    add_transpose_kernel<<<dim3(TLEN / 32, DIM / 32, BATCH), dim3(32, 8)>>>(x, out);
}

// round 16
// speedup vs baseline: 1.0341x; 1.0341x over previous
#include <cuda_runtime.h>
#include <cuda_bf16.h>
#include <cstdint>
#include <math.h>

#define BATCH 2
#define TLEN 2048
#define DIM 1024
#define HEADS 16
#define DH 64
#define WINDOW 32
#define NTOK (BATCH * TLEN)
#define LN_EPS 1e-5f

// ---------------- scratch (device globals; 96 MB fp32 set) ----------------
__device__ float g_h[(size_t)NTOK * DIM];          // LN output, [tok, DIM]
__device__ float g_qkv[(size_t)NTOK * 3 * DIM];    // [tok, 3*DIM]
__device__ float g_att[(size_t)NTOK * DIM];        // attention output
__device__ float g_proj[(size_t)NTOK * DIM];       // (kept; unused by fused path)

// ---------------- 1) LayerNorm + transpose [B,C,T] -> [tok,C] -------------
__global__ void ln_transpose_kernel(const float* __restrict__ x,
                                    const float* __restrict__ w,
                                    const float* __restrict__ bias) {
    const int b  = blockIdx.y;
    const int t0 = blockIdx.x * 32;
    const int tx = threadIdx.x, ty = threadIdx.y;
    const float* xb = x + (size_t)b * DIM * TLEN;

    float s = 0.f, ss = 0.f;
    for (int c = ty; c < DIM; c += 8) {
        float v = xb[(size_t)c * TLEN + t0 + tx];
        s += v; ss += v * v;
    }
    __shared__ float rs[8][32], rq[8][32];
    rs[ty][tx] = s; rq[ty][tx] = ss;
    __syncthreads();
    __shared__ float mu[32], rstd[32];
    if (ty == 0) {
        float a = 0.f, q = 0.f;
        #pragma unroll
        for (int i = 0; i < 8; i++) { a += rs[i][tx]; q += rq[i][tx]; }
        float m   = a / (float)DIM;
        float var = q / (float)DIM - m * m;
        mu[tx]   = m;
        rstd[tx] = rsqrtf(var + LN_EPS);
    }
    __syncthreads();

    __shared__ float tile[32][33];
    for (int c0 = 0; c0 < DIM; c0 += 32) {
        #pragma unroll
        for (int k = 0; k < 4; k++) {
            int cl = ty + 8 * k;
            tile[cl][tx] = xb[(size_t)(c0 + cl) * TLEN + t0 + tx];
        }
        __syncthreads();
        #pragma unroll
        for (int k = 0; k < 4; k++) {
            int tl = ty + 8 * k;
            int c  = c0 + tx;
            float v = (tile[tx][tl] - mu[tl]) * rstd[tl] * w[c] + bias[c];
            g_h[((size_t)b * TLEN + t0 + tl) * DIM + c] = v;
        }
        __syncthreads();
    }
}

// ---------------- 2/5) bf16x3 GEMM: ldmatrix + double-buffered smem -------
// C[M,N] = A[M,K] * B[K,N]; A [tok,K], B native [K,N].
// CTA tile 128x64xk32, 8 warps (4m x 2n), warp tile 32x32, 2-stage smem.
// which==0: write C=g_qkv.  which==1: fused epilogue -> out = C^T + x.
#define SRA 40
#define SRB 72
#define OA_HI 0
#define OA_LO 10240
#define OB_HI 20480
#define OB_LO 25088
#define STG_B 29696
#define GEMM_SMEM (2 * STG_B)       // 59392 bytes (>= 64*132*4 stage)

#define MMA16816(d, a0, a1, a2, a3, b0, b1)                                   \
    asm volatile("mma.sync.aligned.m16n8k16.row.col.f32.bf16.bf16.f32 "      \
                 "{%0,%1,%2,%3}, {%4,%5,%6,%7}, {%8,%9}, {%0,%1,%2,%3};"     \
                 : "+f"(d[0]), "+f"(d[1]), "+f"(d[2]), "+f"(d[3])             \
                 : "r"(a0), "r"(a1), "r"(a2), "r"(a3), "r"(b0), "r"(b1))

#define LDSM4(r0, r1, r2, r3, addr)                                           \
    asm volatile("ldmatrix.sync.aligned.m8n8.x4.shared.b16 {%0,%1,%2,%3}, [%4];" \
                 : "=r"(r0), "=r"(r1), "=r"(r2), "=r"(r3) : "r"(addr))

#define LDSM4T(r0, r1, r2, r3, addr)                                          \
    asm volatile("ldmatrix.sync.aligned.m8n8.x4.trans.shared.b16 {%0,%1,%2,%3}, [%4];" \
                 : "=r"(r0), "=r"(r1), "=r"(r2), "=r"(r3) : "r"(addr))

__device__ __forceinline__ void split2(float fx, float fy,
                                       uint32_t& hi, uint32_t& lo) {
    __nv_bfloat162 h = __floats2bfloat162_rn(fx, fy);
    float2 hf = __bfloat1622float2(h);
    __nv_bfloat162 l = __floats2bfloat162_rn(fx - hf.x, fy - hf.y);
    hi = *(uint32_t*)&h;
    lo = *(uint32_t*)&l;
}

__global__ __launch_bounds__(256)
void sgemm_tc_kernel(int which, const float* __restrict__ Bm, int N,
                     const float* __restrict__ xres, float* __restrict__ outp) {
    const float* __restrict__ A = (which == 0) ? g_h : g_att;
    const int K = DIM;

    extern __shared__ __align__(16) char smx[];
    const uint32_t uS = (uint32_t)__cvta_generic_to_shared(smx);

    const int tid  = threadIdx.x;
    const int warp = tid >> 5, lane = tid & 31;
    const int wm0 = (warp & 3) * 32;
    const int wn0 = (warp >> 2) * 32;
    const int m0 = blockIdx.y * 128;
    const int n0 = blockIdx.x * 64;

    float acc[2][4][4];
    #pragma unroll
    for (int i = 0; i < 2; i++)
        #pragma unroll
        for (int j = 0; j < 4; j++)
            #pragma unroll
            for (int k = 0; k < 4; k++) acc[i][j][k] = 0.f;

    const int g8 = lane >> 3;
    const int lr = lane & 7;
    const int xo = (g8 & 1) * 8;
    const int aRow = wm0 + (g8 & 1) * 8 + lr;
    const int aCol0 = (g8 >> 1) * 8;
    const int bRow = (g8 & 1) * 8 + lr;
    const int bCol = (wn0 + (g8 >> 1) * 8) ^ xo;

    const int ar = tid >> 3;
    const int ac = (tid & 7) * 4;
    const int br = tid >> 4;
    const int bc = (tid & 15) * 4;

    float4 pa[4], pb[2];

    #define FETCH(kt)                                                          \
    do {                                                                       \
        int kb = (kt) * 32;                                                    \
        _Pragma("unroll")                                                      \
        for (int i = 0; i < 4; i++)                                            \
            pa[i] = *(const float4*)&A[(size_t)(m0 + ar + 32 * i) * K + kb + ac]; \
        _Pragma("unroll")                                                      \
        for (int i = 0; i < 2; i++)                                            \
            pb[i] = *(const float4*)&Bm[(size_t)(kb + br + 16 * i) * N + n0 + bc]; \
    } while (0)

    #define STORE(st)                                                          \
    do {                                                                       \
        char* sp = smx + (st) * STG_B;                                         \
        _Pragma("unroll")                                                      \
        for (int i = 0; i < 4; i++) {                                          \
            int row = ar + 32 * i;                                             \
            int col = ac ^ (((row >> 3) & 1) * 8);                             \
            uint32_t h0, l0, h1, l1;                                           \
            split2(pa[i].x, pa[i].y, h0, l0);                                  \
            split2(pa[i].z, pa[i].w, h1, l1);                                  \
            *(uint2*)(sp + OA_HI + (row * SRA + col) * 2) = make_uint2(h0, h1);\
            *(uint2*)(sp + OA_LO + (row * SRA + col) * 2) = make_uint2(l0, l1);\
        }                                                                      \
        _Pragma("unroll")                                                      \
        for (int i = 0; i < 2; i++) {                                          \
            int krow = br + 16 * i;                                            \
            int col = bc ^ (((krow >> 3) & 1) * 8);                            \
            uint32_t h0, l0, h1, l1;                                           \
            split2(pb[i].x, pb[i].y, h0, l0);                                  \
            split2(pb[i].z, pb[i].w, h1, l1);                                  \
            *(uint2*)(sp + OB_HI + (krow * SRB + col) * 2) = make_uint2(h0, h1);\
            *(uint2*)(sp + OB_LO + (krow * SRB + col) * 2) = make_uint2(l0, l1);\
        }                                                                      \
    } while (0)

    const int ntiles = K / 32;
    FETCH(0);
    STORE(0);
    __syncthreads();
    FETCH(1);

    for (int kt = 0; kt < ntiles; kt++) {
        const int cur = kt & 1;
        const uint32_t uStage = uS + cur * STG_B;

        #pragma unroll
        for (int ks = 0; ks < 2; ks++) {
            uint32_t bh[4][2], bl[4][2];
            #pragma unroll
            for (int p = 0; p < 2; p++) {
                uint32_t ba = (uint32_t)(((bRow + ks * 16) * SRB + bCol + p * 16) * 2);
                LDSM4T(bh[2 * p][0], bh[2 * p][1], bh[2 * p + 1][0], bh[2 * p + 1][1],
                       uStage + OB_HI + ba);
                LDSM4T(bl[2 * p][0], bl[2 * p][1], bl[2 * p + 1][0], bl[2 * p + 1][1],
                       uStage + OB_LO + ba);
            }
            #pragma unroll
            for (int mt = 0; mt < 2; mt++) {
                uint32_t aa = (uint32_t)(((aRow + mt * 16) * SRA + ((aCol0 + ks * 16) ^ xo)) * 2);
                uint32_t a0, a1, a2, a3, l0, l1, l2, l3;
                LDSM4(a0, a1, a2, a3, uStage + OA_HI + aa);
                LDSM4(l0, l1, l2, l3, uStage + OA_LO + aa);
                #pragma unroll
                for (int nt = 0; nt < 4; nt++) {
                    MMA16816(acc[mt][nt], a0, a1, a2, a3, bh[nt][0], bh[nt][1]);
                    MMA16816(acc[mt][nt], a0, a1, a2, a3, bl[nt][0], bl[nt][1]);
                    MMA16816(acc[mt][nt], l0, l1, l2, l3, bh[nt][0], bh[nt][1]);
                }
            }
        }
        if (kt + 1 < ntiles) {
            STORE(cur ^ 1);
            if (kt + 2 < ntiles) FETCH(kt + 2);
        }
        __syncthreads();
    }
    #undef FETCH
    #undef STORE

    const int r  = lane >> 2;
    const int c2 = (lane & 3) * 2;

    if (which == 0) {
        #pragma unroll
        for (int mt = 0; mt < 2; mt++)
            #pragma unroll
            for (int nt = 0; nt < 4; nt++) {
                int row = m0 + wm0 + mt * 16 + r;
                int col = n0 + wn0 + nt * 8 + c2;
                float2 v0 = make_float2(acc[mt][nt][0], acc[mt][nt][1]);
                float2 v1 = make_float2(acc[mt][nt][2], acc[mt][nt][3]);
                *(float2*)&g_qkv[(size_t)row * N + col]       = v0;
                *(float2*)&g_qkv[(size_t)(row + 8) * N + col] = v1;
            }
    } else {
        // fused epilogue: stage [col][row] in smem, write out^T + residual
        float* stg = (float*)smx;   // [64][132] floats = 33792 B (barrier above)
        #pragma unroll
        for (int mt = 0; mt < 2; mt++)
            #pragma unroll
            for (int nt = 0; nt < 4; nt++) {
                int row = wm0 + mt * 16 + r;
                int col = wn0 + nt * 8 + c2;
                stg[(col)     * 132 + row]     = acc[mt][nt][0];
                stg[(col + 1) * 132 + row]     = acc[mt][nt][1];
                stg[(col)     * 132 + row + 8] = acc[mt][nt][2];
                stg[(col + 1) * 132 + row + 8] = acc[mt][nt][3];
            }
        __syncthreads();
        const int bb = m0 >> 11;           // batch (2048 tokens each)
        const int tb = m0 & 2047;          // token base within batch
        const int col  = tid >> 2;         // 0..63
        const int row0 = (tid & 3) * 32;   // 0..96
        #pragma unroll
        for (int e = 0; e < 8; e++) {
            int row = row0 + 4 * e;
            float4 v = *(const float4*)&stg[col * 132 + row];
            size_t oidx = ((size_t)bb * DIM + n0 + col) * TLEN + tb + row;
            float4 xr = *(const float4*)&xres[oidx];
            v.x += xr.x; v.y += xr.y; v.z += xr.z; v.w += xr.w;
            *(float4*)&outp[oidx] = v;
        }
    }
}

// ---------------- 4) windowed causal attention + fused RoPE (R14) ---------
__global__ __launch_bounds__(256)
void attn_kernel() {
    const int t0 = blockIdx.x * 32;
    const int bh = blockIdx.y;
    const int b = bh / HEADS, h = bh % HEADS;

    __shared__ float Qs[32][64];
    __shared__ float Ks[64][65];
    __shared__ float Vs[64][65];

    const int tid = threadIdx.x;
    const float FREQ = 9.210340371976184f / 32.0f;   // ln(10000)/32

    for (int i = tid; i < 32 * 32; i += 256) {
        int q = i >> 5, d = i & 31;
        int tpos = t0 + q;
        float inv = expf(-(float)d * FREQ);
        float sn, cs;
        sincosf((float)tpos * inv, &sn, &cs);
        size_t base = ((size_t)(b * TLEN + tpos)) * (3 * DIM) + h * DH + d;
        float v1 = g_qkv[base];
        float v2 = g_qkv[base + 32];
        Qs[q][d]      = v1 * cs - v2 * sn;
        Qs[q][d + 32] = v2 * cs + v1 * sn;
    }
    for (int i = tid; i < 63 * 32; i += 256) {
        int rr = i >> 5, d = i & 31;
        int kpos = t0 - 31 + rr;
        float k1 = 0.f, k2 = 0.f;
        if (kpos >= 0) {
            float inv = expf(-(float)d * FREQ);
            float sn, cs;
            sincosf((float)kpos * inv, &sn, &cs);
            size_t off = ((size_t)(b * TLEN + kpos)) * (3 * DIM) + DIM + h * DH + d;
            float v1 = g_qkv[off];
            float v2 = g_qkv[off + 32];
            k1 = v1 * cs - v2 * sn;
            k2 = v2 * cs + v1 * sn;
        }
        Ks[rr][d]      = k1;
        Ks[rr][d + 32] = k2;
    }
    for (int i = tid; i < 63 * 64; i += 256) {
        int rr = i >> 6, d = i & 63;
        int kpos = t0 - 31 + rr;
        float vv = 0.f;
        if (kpos >= 0)
            vv = g_qkv[((size_t)(b * TLEN + kpos)) * (3 * DIM) + 2 * DIM + h * DH + d];
        Vs[rr][d] = vv;
    }
    __syncthreads();

    const int warp = tid >> 5, lane = tid & 31;
    #pragma unroll
    for (int j = 0; j < 4; j++) {
        const int ql   = warp * 4 + j;
        const int qpos = t0 + ql;
        const int rr   = ql + lane;
        const int kpos = qpos - 31 + lane;
        const bool valid = (kpos >= 0);

        float s = 0.f;
        #pragma unroll
        for (int d = 0; d < 64; d++) s = fmaf(Qs[ql][d], Ks[rr][d], s);
        s *= 0.125f;
        s = valid ? s : -INFINITY;

        float m = s;
        #pragma unroll
        for (int o = 16; o; o >>= 1) m = fmaxf(m, __shfl_xor_sync(0xffffffffu, m, o));
        float p = valid ? expf(s - m) : 0.f;
        float sum = p;
        #pragma unroll
        for (int o = 16; o; o >>= 1) sum += __shfl_xor_sync(0xffffffffu, sum, o);
        p /= sum;

        float o0 = 0.f, o1 = 0.f;
        #pragma unroll
        for (int jj = 0; jj < 32; jj++) {
            float pj = __shfl_sync(0xffffffffu, p, jj);
            int rj = ql + jj;
            o0 = fmaf(pj, Vs[rj][2 * lane],     o0);
            o1 = fmaf(pj, Vs[rj][2 * lane + 1], o1);
        }
        size_t oo = ((size_t)(b * TLEN + qpos)) * DIM + h * DH + 2 * lane;
        g_att[oo]     = o0;
        g_att[oo + 1] = o1;
    }
}

// ---------------- launch ---------------------------------------------------
extern "C" void kernel_launch(void* const* d_in, const int* in_sizes, int n_in,
                              void* d_out, int out_size) {
    const float* x     = (const float*)d_in[0];
    const float* ln_w  = (const float*)d_in[1];
    const float* ln_b  = (const float*)d_in[2];
    const float* w_qkv = (const float*)d_in[3];
    const float* w_out = (const float*)d_in[4];
    float* out = (float*)d_out;

    cudaFuncSetAttribute(sgemm_tc_kernel,
                         cudaFuncAttributeMaxDynamicSharedMemorySize, GEMM_SMEM);

    ln_transpose_kernel<<<dim3(TLEN / 32, BATCH), dim3(32, 8)>>>(x, ln_w, ln_b);

    // QKV GEMM: [4096,1024] x [1024,3072] -> g_qkv
    sgemm_tc_kernel<<<dim3((3 * DIM) / 64, NTOK / 128), 256, GEMM_SMEM>>>(
        0, w_qkv, 3 * DIM, nullptr, nullptr);

    // attention with fused RoPE -> g_att
    attn_kernel<<<dim3(TLEN / 32, BATCH * HEADS), 256>>>();

    // out projection + fused transpose/residual: out = (g_att x w_out)^T + x
    sgemm_tc_kernel<<<dim3(DIM / 64, NTOK / 128), 256, GEMM_SMEM>>>(
        1, w_out, DIM, x, out);
}

// round 17
// speedup vs baseline: 1.0392x; 1.0049x over previous
#include <cuda_runtime.h>
#include <cuda_bf16.h>
#include <cstdint>
#include <math.h>

#define BATCH 2
#define TLEN 2048
#define DIM 1024
#define HEADS 16
#define DH 64
#define WINDOW 32
#define NTOK (BATCH * TLEN)
#define LN_EPS 1e-5f

// ---------------- scratch (device globals; 96 MB fp32 set) ----------------
__device__ float g_h[(size_t)NTOK * DIM];          // LN output, [tok, DIM]
__device__ float g_qkv[(size_t)NTOK * 3 * DIM];    // [tok, 3*DIM]
__device__ float g_att[(size_t)NTOK * DIM];        // attention output
__device__ float g_proj[(size_t)NTOK * DIM];       // (kept; unused by fused path)

// ---------------- 1) LayerNorm + transpose [B,C,T] -> [tok,C] -------------
__global__ void ln_transpose_kernel(const float* __restrict__ x,
                                    const float* __restrict__ w,
                                    const float* __restrict__ bias) {
    const int b  = blockIdx.y;
    const int t0 = blockIdx.x * 32;
    const int tx = threadIdx.x, ty = threadIdx.y;
    const float* xb = x + (size_t)b * DIM * TLEN;

    float s = 0.f, ss = 0.f;
    for (int c = ty; c < DIM; c += 8) {
        float v = xb[(size_t)c * TLEN + t0 + tx];
        s += v; ss += v * v;
    }
    __shared__ float rs[8][32], rq[8][32];
    rs[ty][tx] = s; rq[ty][tx] = ss;
    __syncthreads();
    __shared__ float mu[32], rstd[32];
    if (ty == 0) {
        float a = 0.f, q = 0.f;
        #pragma unroll
        for (int i = 0; i < 8; i++) { a += rs[i][tx]; q += rq[i][tx]; }
        float m   = a / (float)DIM;
        float var = q / (float)DIM - m * m;
        mu[tx]   = m;
        rstd[tx] = rsqrtf(var + LN_EPS);
    }
    __syncthreads();

    __shared__ float tile[32][33];
    for (int c0 = 0; c0 < DIM; c0 += 32) {
        #pragma unroll
        for (int k = 0; k < 4; k++) {
            int cl = ty + 8 * k;
            tile[cl][tx] = xb[(size_t)(c0 + cl) * TLEN + t0 + tx];
        }
        __syncthreads();
        #pragma unroll
        for (int k = 0; k < 4; k++) {
            int tl = ty + 8 * k;
            int c  = c0 + tx;
            float v = (tile[tx][tl] - mu[tl]) * rstd[tl] * w[c] + bias[c];
            g_h[((size_t)b * TLEN + t0 + tl) * DIM + c] = v;
        }
        __syncthreads();
    }
}

// ---------------- 2/5) bf16x3 GEMM: ldmatrix + double-buffered smem -------
// C[M,N] = A[M,K] * B[K,N]; A [tok,K], B native [K,N].
// CTA tile 128x64xk32, 8 warps (4m x 2n), warp tile 32x32, 2-stage smem.
// which==0: write C=g_qkv.  which==1: fused epilogue -> out = C^T + x.
#define SRA 40
#define SRB 72
#define OA_HI 0
#define OA_LO 10240
#define OB_HI 20480
#define OB_LO 25088
#define STG_B 29696
#define GEMM_SMEM (2 * STG_B)       // 59392 bytes (>= 64*132*4 stage)

#define MMA16816(d, a0, a1, a2, a3, b0, b1)                                   \
    asm volatile("mma.sync.aligned.m16n8k16.row.col.f32.bf16.bf16.f32 "      \
                 "{%0,%1,%2,%3}, {%4,%5,%6,%7}, {%8,%9}, {%0,%1,%2,%3};"     \
                 : "+f"(d[0]), "+f"(d[1]), "+f"(d[2]), "+f"(d[3])             \
                 : "r"(a0), "r"(a1), "r"(a2), "r"(a3), "r"(b0), "r"(b1))

#define LDSM4(r0, r1, r2, r3, addr)                                           \
    asm volatile("ldmatrix.sync.aligned.m8n8.x4.shared.b16 {%0,%1,%2,%3}, [%4];" \
                 : "=r"(r0), "=r"(r1), "=r"(r2), "=r"(r3) : "r"(addr))

#define LDSM4T(r0, r1, r2, r3, addr)                                          \
    asm volatile("ldmatrix.sync.aligned.m8n8.x4.trans.shared.b16 {%0,%1,%2,%3}, [%4];" \
                 : "=r"(r0), "=r"(r1), "=r"(r2), "=r"(r3) : "r"(addr))

__device__ __forceinline__ void split2(float fx, float fy,
                                       uint32_t& hi, uint32_t& lo) {
    __nv_bfloat162 h = __floats2bfloat162_rn(fx, fy);
    float2 hf = __bfloat1622float2(h);
    __nv_bfloat162 l = __floats2bfloat162_rn(fx - hf.x, fy - hf.y);
    hi = *(uint32_t*)&h;
    lo = *(uint32_t*)&l;
}

__global__ __launch_bounds__(256)
void sgemm_tc_kernel(int which, const float* __restrict__ Bm, int N,
                     const float* __restrict__ xres, float* __restrict__ outp) {
    const float* __restrict__ A = (which == 0) ? g_h : g_att;
    const int K = DIM;

    extern __shared__ __align__(16) char smx[];
    const uint32_t uS = (uint32_t)__cvta_generic_to_shared(smx);

    const int tid  = threadIdx.x;
    const int warp = tid >> 5, lane = tid & 31;
    const int wm0 = (warp & 3) * 32;
    const int wn0 = (warp >> 2) * 32;
    const int m0 = blockIdx.y * 128;
    const int n0 = blockIdx.x * 64;

    float acc[2][4][4];
    #pragma unroll
    for (int i = 0; i < 2; i++)
        #pragma unroll
        for (int j = 0; j < 4; j++)
            #pragma unroll
            for (int k = 0; k < 4; k++) acc[i][j][k] = 0.f;

    const int g8 = lane >> 3;
    const int lr = lane & 7;
    const int xo = (g8 & 1) * 8;
    const int aRow = wm0 + (g8 & 1) * 8 + lr;
    const int aCol0 = (g8 >> 1) * 8;
    const int bRow = (g8 & 1) * 8 + lr;
    const int bCol = (wn0 + (g8 >> 1) * 8) ^ xo;

    const int ar = tid >> 3;
    const int ac = (tid & 7) * 4;
    const int br = tid >> 4;
    const int bc = (tid & 15) * 4;

    float4 pa[4], pb[2];

    #define FETCH(kt)                                                          \
    do {                                                                       \
        int kb = (kt) * 32;                                                    \
        _Pragma("unroll")                                                      \
        for (int i = 0; i < 4; i++)                                            \
            pa[i] = *(const float4*)&A[(size_t)(m0 + ar + 32 * i) * K + kb + ac]; \
        _Pragma("unroll")                                                      \
        for (int i = 0; i < 2; i++)                                            \
            pb[i] = *(const float4*)&Bm[(size_t)(kb + br + 16 * i) * N + n0 + bc]; \
    } while (0)

    #define STORE(st)                                                          \
    do {                                                                       \
        char* sp = smx + (st) * STG_B;                                         \
        _Pragma("unroll")                                                      \
        for (int i = 0; i < 4; i++) {                                          \
            int row = ar + 32 * i;                                             \
            int col = ac ^ (((row >> 3) & 1) * 8);                             \
            uint32_t h0, l0, h1, l1;                                           \
            split2(pa[i].x, pa[i].y, h0, l0);                                  \
            split2(pa[i].z, pa[i].w, h1, l1);                                  \
            *(uint2*)(sp + OA_HI + (row * SRA + col) * 2) = make_uint2(h0, h1);\
            *(uint2*)(sp + OA_LO + (row * SRA + col) * 2) = make_uint2(l0, l1);\
        }                                                                      \
        _Pragma("unroll")                                                      \
        for (int i = 0; i < 2; i++) {                                          \
            int krow = br + 16 * i;                                            \
            int col = bc ^ (((krow >> 3) & 1) * 8);                            \
            uint32_t h0, l0, h1, l1;                                           \
            split2(pb[i].x, pb[i].y, h0, l0);                                  \
            split2(pb[i].z, pb[i].w, h1, l1);                                  \
            *(uint2*)(sp + OB_HI + (krow * SRB + col) * 2) = make_uint2(h0, h1);\
            *(uint2*)(sp + OB_LO + (krow * SRB + col) * 2) = make_uint2(l0, l1);\
        }                                                                      \
    } while (0)

    const int ntiles = K / 32;
    FETCH(0);
    STORE(0);
    __syncthreads();
    FETCH(1);

    for (int kt = 0; kt < ntiles; kt++) {
        const int cur = kt & 1;
        const uint32_t uStage = uS + cur * STG_B;

        #pragma unroll
        for (int ks = 0; ks < 2; ks++) {
            uint32_t bh[4][2], bl[4][2];
            #pragma unroll
            for (int p = 0; p < 2; p++) {
                uint32_t ba = (uint32_t)(((bRow + ks * 16) * SRB + bCol + p * 16) * 2);
                LDSM4T(bh[2 * p][0], bh[2 * p][1], bh[2 * p + 1][0], bh[2 * p + 1][1],
                       uStage + OB_HI + ba);
                LDSM4T(bl[2 * p][0], bl[2 * p][1], bl[2 * p + 1][0], bl[2 * p + 1][1],
                       uStage + OB_LO + ba);
            }
            #pragma unroll
            for (int mt = 0; mt < 2; mt++) {
                uint32_t aa = (uint32_t)(((aRow + mt * 16) * SRA + ((aCol0 + ks * 16) ^ xo)) * 2);
                uint32_t a0, a1, a2, a3, l0, l1, l2, l3;
                LDSM4(a0, a1, a2, a3, uStage + OA_HI + aa);
                LDSM4(l0, l1, l2, l3, uStage + OA_LO + aa);
                #pragma unroll
                for (int nt = 0; nt < 4; nt++) {
                    MMA16816(acc[mt][nt], a0, a1, a2, a3, bh[nt][0], bh[nt][1]);
                    MMA16816(acc[mt][nt], a0, a1, a2, a3, bl[nt][0], bl[nt][1]);
                    MMA16816(acc[mt][nt], l0, l1, l2, l3, bh[nt][0], bh[nt][1]);
                }
            }
        }
        if (kt + 1 < ntiles) {
            STORE(cur ^ 1);
            if (kt + 2 < ntiles) FETCH(kt + 2);
        }
        __syncthreads();
    }
    #undef FETCH
    #undef STORE

    const int r  = lane >> 2;
    const int c2 = (lane & 3) * 2;

    if (which == 0) {
        #pragma unroll
        for (int mt = 0; mt < 2; mt++)
            #pragma unroll
            for (int nt = 0; nt < 4; nt++) {
                int row = m0 + wm0 + mt * 16 + r;
                int col = n0 + wn0 + nt * 8 + c2;
                float2 v0 = make_float2(acc[mt][nt][0], acc[mt][nt][1]);
                float2 v1 = make_float2(acc[mt][nt][2], acc[mt][nt][3]);
                *(float2*)&g_qkv[(size_t)row * N + col]       = v0;
                *(float2*)&g_qkv[(size_t)(row + 8) * N + col] = v1;
            }
    } else {
        // fused epilogue: stage [col][row] in smem, write out^T + residual
        float* stg = (float*)smx;   // [64][132] floats = 33792 B (barrier above)
        #pragma unroll
        for (int mt = 0; mt < 2; mt++)
            #pragma unroll
            for (int nt = 0; nt < 4; nt++) {
                int row = wm0 + mt * 16 + r;
                int col = wn0 + nt * 8 + c2;
                stg[(col)     * 132 + row]     = acc[mt][nt][0];
                stg[(col + 1) * 132 + row]     = acc[mt][nt][1];
                stg[(col)     * 132 + row + 8] = acc[mt][nt][2];
                stg[(col + 1) * 132 + row + 8] = acc[mt][nt][3];
            }
        __syncthreads();
        const int bb = m0 >> 11;           // batch (2048 tokens each)
        const int tb = m0 & 2047;          // token base within batch
        const int col  = tid >> 2;         // 0..63
        const int row0 = (tid & 3) * 32;   // 0..96
        #pragma unroll
        for (int e = 0; e < 8; e++) {
            int row = row0 + 4 * e;
            float4 v = *(const float4*)&stg[col * 132 + row];
            size_t oidx = ((size_t)bb * DIM + n0 + col) * TLEN + tb + row;
            float4 xr = *(const float4*)&xres[oidx];
            v.x += xr.x; v.y += xr.y; v.z += xr.z; v.w += xr.w;
            *(float4*)&outp[oidx] = v;
        }
    }
}

// ---------------- 4) windowed causal attention + fused RoPE (R14) ---------
__global__ __launch_bounds__(256)
void attn_kernel() {
    const int t0 = blockIdx.x * 32;
    const int bh = blockIdx.y;
    const int b = bh / HEADS, h = bh % HEADS;

    __shared__ float Qs[32][64];
    __shared__ float Ks[64][65];
    __shared__ float Vs[64][65];

    const int tid = threadIdx.x;
    const float FREQ = 9.210340371976184f / 32.0f;   // ln(10000)/32

    for (int i = tid; i < 32 * 32; i += 256) {
        int q = i >> 5, d = i & 31;
        int tpos = t0 + q;
        float inv = expf(-(float)d * FREQ);
        float sn, cs;
        sincosf((float)tpos * inv, &sn, &cs);
        size_t base = ((size_t)(b * TLEN + tpos)) * (3 * DIM) + h * DH + d;
        float v1 = g_qkv[base];
        float v2 = g_qkv[base + 32];
        Qs[q][d]      = v1 * cs - v2 * sn;
        Qs[q][d + 32] = v2 * cs + v1 * sn;
    }
    for (int i = tid; i < 63 * 32; i += 256) {
        int rr = i >> 5, d = i & 31;
        int kpos = t0 - 31 + rr;
        float k1 = 0.f, k2 = 0.f;
        if (kpos >= 0) {
            float inv = expf(-(float)d * FREQ);
            float sn, cs;
            sincosf((float)kpos * inv, &sn, &cs);
            size_t off = ((size_t)(b * TLEN + kpos)) * (3 * DIM) + DIM + h * DH + d;
            float v1 = g_qkv[off];
            float v2 = g_qkv[off + 32];
            k1 = v1 * cs - v2 * sn;
            k2 = v2 * cs + v1 * sn;
        }
        Ks[rr][d]      = k1;
        Ks[rr][d + 32] = k2;
    }
    for (int i = tid; i < 63 * 64; i += 256) {
        int rr = i >> 6, d = i & 63;
        int kpos = t0 - 31 + rr;
        float vv = 0.f;
        if (kpos >= 0)
            vv = g_qkv[((size_t)(b * TLEN + kpos)) * (3 * DIM) + 2 * DIM + h * DH + d];
        Vs[rr][d] = vv;
    }
    __syncthreads();

    const int warp = tid >> 5, lane = tid & 31;
    #pragma unroll
    for (int j = 0; j < 4; j++) {
        const int ql   = warp * 4 + j;
        const int qpos = t0 + ql;
        const int rr   = ql + lane;
        const int kpos = qpos - 31 + lane;
        const bool valid = (kpos >= 0);

        float s = 0.f;
        #pragma unroll
        for (int d = 0; d < 64; d++) s = fmaf(Qs[ql][d], Ks[rr][d], s);
        s *= 0.125f;
        s = valid ? s : -INFINITY;

        float m = s;
        #pragma unroll
        for (int o = 16; o; o >>= 1) m = fmaxf(m, __shfl_xor_sync(0xffffffffu, m, o));
        float p = valid ? expf(s - m) : 0.f;
        float sum = p;
        #pragma unroll
        for (int o = 16; o; o >>= 1) sum += __shfl_xor_sync(0xffffffffu, sum, o);
        p /= sum;

        float o0 = 0.f, o1 = 0.f;
        #pragma unroll
        for (int jj = 0; jj < 32; jj++) {
            float pj = __shfl_sync(0xffffffffu, p, jj);
            int rj = ql + jj;
            o0 = fmaf(pj, Vs[rj][2 * lane],     o0);
            o1 = fmaf(pj, Vs[rj][2 * lane + 1], o1);
        }
        size_t oo = ((size_t)(b * TLEN + qpos)) * DIM + h * DH + 2 * lane;
        g_att[oo]     = o0;
        g_att[oo + 1] = o1;
    }
}

// ---------------- launch ---------------------------------------------------
extern "C" void kernel_launch(void* const* d_in, const int* in_sizes, int n_in,
                              void* d_out, int out_size) {
    const float* x     = (const float*)d_in[0];
    const float* ln_w  = (const float*)d_in[1];
    const float* ln_b  = (const float*)d_in[2];
    const float* w_qkv = (const float*)d_in[3];
    const float* w_out = (const float*)d_in[4];
    float* out = (float*)d_out;

    cudaFuncSetAttribute(sgemm_tc_kernel,
                         cudaFuncAttributeMaxDynamicSharedMemorySize, GEMM_SMEM);

    ln_transpose_kernel<<<dim3(TLEN / 32, BATCH), dim3(32, 8)>>>(x, ln_w, ln_b);

    // QKV GEMM: [4096,1024] x [1024,3072] -> g_qkv
    sgemm_tc_kernel<<<dim3((3 * DIM) / 64, NTOK / 128), 256, GEMM_SMEM>>>(
        0, w_qkv, 3 * DIM, nullptr, nullptr);

    // attention with fused RoPE -> g_att
    attn_kernel<<<dim3(TLEN / 32, BATCH * HEADS), 256>>>();

    // out projection + fused transpose/residual: out = (g_att x w_out)^T + x
    sgemm_tc_kernel<<<dim3(DIM / 64, NTOK / 128), 256, GEMM_SMEM>>>(
        1, w_out, DIM, x, out);
}